// round 7
// baseline (speedup 1.0000x reference)
#include <cuda_runtime.h>
#include <cuda_bf16.h>
#include <math.h>
#include <stdint.h>

#define BB 32
#define TT 2048
#define DIN 64
#define HH 1024
#define DOUT 64
#define NSTEPS 60
#define C1 8
#define C2 16
#define C3 32
#define K1 4
#define K2 8
#define K3 16
#define LEN1 2045
#define LEN2 2038
#define LL 2023
#define G4 4096

/* K-padded (multiple of 32) concat widths */
#define KT1P 1152   /* [ctx1(32) prev_y(64) h1(1024) pad(32)] */
#define KT23P 2112  /* [ctx(32) h_prev(1024) h_self(1024) pad(32)] */

typedef unsigned long long ull;

/* ------------- static device scratch (no runtime allocation) ------------- */
__device__ __align__(16) __nv_bfloat16 d_W1hi[G4 * KT1P];
__device__ __align__(16) __nv_bfloat16 d_W1lo[G4 * KT1P];
__device__ __align__(16) __nv_bfloat16 d_W2hi[G4 * KT23P];
__device__ __align__(16) __nv_bfloat16 d_W2lo[G4 * KT23P];
__device__ __align__(16) __nv_bfloat16 d_W3hi[G4 * KT23P];
__device__ __align__(16) __nv_bfloat16 d_W3lo[G4 * KT23P];
__device__ __align__(16) __nv_bfloat16 d_x1hi[BB * KT1P];
__device__ __align__(16) __nv_bfloat16 d_x1lo[BB * KT1P];
__device__ __align__(16) __nv_bfloat16 d_x2hi[BB * KT23P];
__device__ __align__(16) __nv_bfloat16 d_x2lo[BB * KT23P];
__device__ __align__(16) __nv_bfloat16 d_x3hi[BB * KT23P];
__device__ __align__(16) __nv_bfloat16 d_x3lo[BB * KT23P];
__device__ __align__(16) float d_gp[2][G4 * BB];
__device__ __align__(16) float d_cbias1[G4];
__device__ __align__(16) float d_cbias2[G4];
__device__ __align__(16) float d_cbias3[G4];
__device__ __align__(16) float d_woutT[HH * DOUT];
__device__ __align__(16) float d_buf1[BB * C1 * LEN1];
__device__ __align__(16) float d_buf2[BB * C2 * LEN2];
__device__ __align__(16) float d_enc[BB * LL * C3];
__device__ __align__(16) float d_h1[BB * HH];
__device__ __align__(16) float d_c1[BB * HH];
__device__ __align__(16) float d_h2[BB * HH];
__device__ __align__(16) float d_c2[BB * HH];
__device__ __align__(16) float d_h3[BB * HH];
__device__ __align__(16) float d_c3[BB * HH];

/* ---------------------------- helpers ------------------------------------ */
__device__ __forceinline__ float sigf(float x) { return 1.f / (1.f + expf(-x)); }

__device__ __forceinline__ void split_bf16(float v, __nv_bfloat16& hi, __nv_bfloat16& lo) {
    hi = __float2bfloat16(v);
    lo = __float2bfloat16(v - __bfloat162float(hi));
}

/* m16n8k16 row.col bf16 MMA, fp32 accumulate (standard PTX, sm_80+) */
__device__ __forceinline__ void mma16816(float* d, const uint32_t* a, const uint32_t* b) {
    asm volatile(
        "mma.sync.aligned.m16n8k16.row.col.f32.bf16.bf16.f32 "
        "{%0,%1,%2,%3}, {%4,%5,%6,%7}, {%8,%9}, {%0,%1,%2,%3};\n"
        : "+f"(d[0]), "+f"(d[1]), "+f"(d[2]), "+f"(d[3])
        : "r"(a[0]), "r"(a[1]), "r"(a[2]), "r"(a[3]), "r"(b[0]), "r"(b[1]));
}

__device__ __forceinline__ uint32_t ldu32(const __nv_bfloat16* p) {
    return *(const uint32_t*)p;
}

/* ------------------- fused setup: weight split + init -------------------- */
__global__ void setup_kernel(const float* __restrict__ x,
                             const float* __restrict__ wih1, const float* __restrict__ whh1,
                             const float* __restrict__ wih2, const float* __restrict__ whh2,
                             const float* __restrict__ wih3, const float* __restrict__ whh3,
                             const float* __restrict__ bih1, const float* __restrict__ bhh1,
                             const float* __restrict__ bih2, const float* __restrict__ bhh2,
                             const float* __restrict__ bih3, const float* __restrict__ bhh3,
                             const float* __restrict__ wout) {
    const size_t SW1 = (size_t)G4 * KT1P;
    const size_t SW23 = (size_t)G4 * KT23P;
    const size_t SB = 3 * G4;
    const size_t SO = HH * DOUT;
    const size_t SH = 6 * BB * HH;
    const size_t SX1 = BB * KT1P;
    const size_t SX23 = BB * KT23P;
    const size_t TOTAL = SW1 + 2 * SW23 + SB + SO + SH + SX1 + 2 * SX23;
    for (size_t idx = (size_t)blockIdx.x * blockDim.x + threadIdx.x; idx < TOTAL;
         idx += (size_t)gridDim.x * blockDim.x) {
        size_t t = idx;
        if (t < SW1 + 2 * SW23) {
            const float *wih, *whh;
            __nv_bfloat16 *dhi, *dlo;
            int kt, kx;
            if (t < SW1) { dhi = d_W1hi; dlo = d_W1lo; wih = wih1; whh = whh1; kt = KT1P; kx = C3 + DIN; }
            else if (t < SW1 + SW23) { t -= SW1; dhi = d_W2hi; dlo = d_W2lo; wih = wih2; whh = whh2; kt = KT23P; kx = C3 + HH; }
            else { t -= SW1 + SW23; dhi = d_W3hi; dlo = d_W3lo; wih = wih3; whh = whh3; kt = KT23P; kx = C3 + HH; }
            int n = (int)(t / kt), col = (int)(t % kt);
            float v;
            if (col < kx) v = wih[(size_t)n * kx + col];
            else if (col < kx + HH) v = whh[(size_t)n * HH + (col - kx)];
            else v = 0.f;
            __nv_bfloat16 hi, lo;
            split_bf16(v, hi, lo);
            dhi[t] = hi; dlo[t] = lo;
            continue;
        }
        t -= SW1 + 2 * SW23;
        if (t < SB) {
            int which = (int)(t / G4), j = (int)(t % G4);
            if (which == 0) d_cbias1[j] = bih1[j] + bhh1[j];
            else if (which == 1) d_cbias2[j] = bih2[j] + bhh2[j];
            else d_cbias3[j] = bih3[j] + bhh3[j];
            continue;
        }
        t -= SB;
        if (t < SO) {
            int hh = (int)(t / DOUT), d = (int)(t % DOUT);
            d_woutT[t] = wout[(size_t)d * HH + hh];
            continue;
        }
        t -= SO;
        if (t < SH) {
            int which = (int)(t / (BB * HH));
            int off = (int)(t % (BB * HH));
            float* p = which == 0 ? d_h1 : which == 1 ? d_c1 : which == 2 ? d_h2
                     : which == 3 ? d_c2 : which == 4 ? d_h3 : d_c3;
            p[off] = 0.f;
            continue;
        }
        t -= SH;
        if (t < SX1) {
            int b = (int)(t / KT1P), col = (int)(t % KT1P);
            float v = 0.f;
            if (col >= 32 && col < 96)
                v = x[((size_t)b * TT + (TT - 1)) * DIN + (col - 32)];
            __nv_bfloat16 hi, lo;
            split_bf16(v, hi, lo);
            d_x1hi[t] = hi; d_x1lo[t] = lo;
            continue;
        }
        t -= SX1;
        if (t < SX23) { d_x2hi[t] = __float2bfloat16(0.f); d_x2lo[t] = __float2bfloat16(0.f); }
        else { t -= SX23; d_x3hi[t] = __float2bfloat16(0.f); d_x3lo[t] = __float2bfloat16(0.f); }
    }
}

/* ------------------------------ conv stack ------------------------------- */
__global__ void conv1_kernel(const float* __restrict__ x, const float* __restrict__ w,
                             const float* __restrict__ bias) {
    __shared__ float ws[DIN * K1];
    int c = blockIdx.y, b = blockIdx.z, tid = threadIdx.x;
    if (tid < DIN * K1) ws[tid] = w[c * DIN * K1 + tid];
    __syncthreads();
    int t = blockIdx.x * 256 + tid;
    if (t >= LEN1) return;
    const float* xp = x + ((size_t)b * TT + t) * DIN;
    float acc = bias[c];
#pragma unroll
    for (int k = 0; k < K1; k++)
#pragma unroll
        for (int i = 0; i < DIN; i++) acc += xp[k * DIN + i] * ws[i * K1 + k];
    d_buf1[((size_t)b * C1 + c) * LEN1 + t] = fmaxf(acc, 0.f);
}

__global__ void conv2_kernel(const float* __restrict__ w, const float* __restrict__ bias) {
    __shared__ float ws[C1 * K2];
    int c = blockIdx.y, b = blockIdx.z, tid = threadIdx.x;
    if (tid < C1 * K2) ws[tid] = w[c * C1 * K2 + tid];
    __syncthreads();
    int t = blockIdx.x * 256 + tid;
    if (t >= LEN2) return;
    float acc = bias[c];
    const float* ip = d_buf1 + (size_t)b * C1 * LEN1;
#pragma unroll
    for (int i = 0; i < C1; i++) {
        const float* row = ip + i * LEN1 + t;
#pragma unroll
        for (int k = 0; k < K2; k++) acc += row[k] * ws[i * K2 + k];
    }
    d_buf2[((size_t)b * C2 + c) * LEN2 + t] = fmaxf(acc, 0.f);
}

__global__ void conv3_kernel(const float* __restrict__ w, const float* __restrict__ bias) {
    __shared__ float ws[C3 * 257];
    int b = blockIdx.y, tid = threadIdx.x;
    for (int i = tid; i < C3 * C2 * K3; i += 256) {
        int c = i / (C2 * K3), r = i % (C2 * K3);
        ws[c * 257 + r] = w[i];
    }
    __syncthreads();
    int c = tid & 31, tl = tid >> 5;
    int t = blockIdx.x * 8 + tl;
    if (t >= LL) return;
    float acc = bias[c];
    const float* ip = d_buf2 + (size_t)b * C2 * LEN2;
    const float* wp = ws + c * 257;
#pragma unroll
    for (int i = 0; i < C2; i++) {
        const float* row = ip + i * LEN2 + t;
#pragma unroll
        for (int k = 0; k < K3; k++) acc += row[k] * wp[i * K3 + k];
    }
    d_enc[((size_t)b * LL + t) * C3 + c] = fmaxf(acc, 0.f);
}

/* -------------- per-step prologue: 3x attention + y of prev step --------- */
__global__ __launch_bounds__(256) void pre_kernel(const float* __restrict__ wa1,
                                                  const float* __restrict__ wa2,
                                                  const float* __restrict__ wa3,
                                                  const float* __restrict__ bout,
                                                  int s, float* __restrict__ out) {
    __shared__ float red[256];
    __shared__ float hp[32];
    __shared__ float sc[LL];
    __shared__ float stot;
    int blk = blockIdx.x, tid = threadIdx.x;
    if (blk < 96) {
        int j = blk >> 5, b = blk & 31;
        const float* hb = (j == 0 ? d_h1 : j == 1 ? d_h2 : d_h3) + b * HH;
        const float* wa = j == 0 ? wa1 : j == 1 ? wa2 : wa3;
        int d = tid & 31, seg = tid >> 5;
        float part = 0.f;
        for (int hh = seg * 128; hh < seg * 128 + 128; hh++)
            part += hb[hh] * wa[hh * 32 + d];
        red[tid] = part;
        __syncthreads();
        if (tid < 32) {
            float sm = 0.f;
#pragma unroll
            for (int q = 0; q < 8; q++) sm += red[q * 32 + tid];
            hp[tid] = sm;
        }
        __syncthreads();
        const float* eb = d_enc + (size_t)b * LL * C3;
        float mx = -1e30f;
        for (int l = tid; l < LL; l += 256) {
            const float4* r = (const float4*)(eb + l * 32);
            float acc = 0.f;
#pragma unroll
            for (int q = 0; q < 8; q++) {
                float4 v = r[q];
                acc += v.x * hp[4 * q] + v.y * hp[4 * q + 1] + v.z * hp[4 * q + 2] +
                       v.w * hp[4 * q + 3];
            }
            sc[l] = acc;
            mx = fmaxf(mx, acc);
        }
        red[tid] = mx;
        __syncthreads();
        for (int st = 128; st > 0; st >>= 1) {
            if (tid < st) red[tid] = fmaxf(red[tid], red[tid + st]);
            __syncthreads();
        }
        mx = red[0];
        __syncthreads();
        float ls = 0.f;
        for (int l = tid; l < LL; l += 256) {
            float e = expf(sc[l] - mx);
            sc[l] = e;
            ls += e;
        }
        red[tid] = ls;
        __syncthreads();
        for (int st = 128; st > 0; st >>= 1) {
            if (tid < st) red[tid] += red[tid + st];
            __syncthreads();
        }
        if (tid == 0) stot = red[0];
        __syncthreads();
        float inv = 1.f / stot;
        int g2 = tid >> 5;
        d = tid & 31;
        float ca = 0.f;
        for (int l = g2; l < LL; l += 8) ca += sc[l] * eb[l * 32 + d];
        __syncthreads();
        red[tid] = ca;
        __syncthreads();
        if (tid < 32) {
            float sm = 0.f;
#pragma unroll
            for (int q = 0; q < 8; q++) sm += red[q * 32 + tid];
            float v = sm * inv;
            __nv_bfloat16 hi, lo;
            split_bf16(v, hi, lo);
            if (j == 0) { d_x1hi[b * KT1P + tid] = hi; d_x1lo[b * KT1P + tid] = lo; }
            else if (j == 1) { d_x2hi[b * KT23P + tid] = hi; d_x2lo[b * KT23P + tid] = lo; }
            else { d_x3hi[b * KT23P + tid] = hi; d_x3lo[b * KT23P + tid] = lo; }
        }
    } else {
        if (s == 0) return;
        int b = blk - 96;
        int d = tid & 63, seg = tid >> 6;
        const float* hb = d_h3 + b * HH;
        float part = 0.f;
        for (int hh = seg * 256; hh < seg * 256 + 256; hh++)
            part += hb[hh] * d_woutT[hh * DOUT + d];
        red[tid] = part;
        __syncthreads();
        if (tid < 64) {
            float y = bout[tid];
#pragma unroll
            for (int q = 0; q < 4; q++) y += red[q * 64 + tid];
            out[((size_t)b * NSTEPS + (s - 1)) * DOUT + tid] = y;
            __nv_bfloat16 hi, lo;
            split_bf16(y, hi, lo);
            d_x1hi[b * KT1P + 32 + tid] = hi;
            d_x1lo[b * KT1P + 32 + tid] = lo;
        }
    }
}

/* --------- HMMA bf16-split GEMM: gpart[kh] = Wcat_kh @ xin_kh^T ---------- */
/* grid (64, 2) x 128 thr. Warp: 16 W-rows x 32 batches x K/2.               */
__global__ __launch_bounds__(128) void mm_hmma(int cell) {
    const __nv_bfloat16 *Whi, *Wlo, *Xhi, *Xlo;
    int KT;
    if (cell == 0) { Whi = d_W1hi; Wlo = d_W1lo; Xhi = d_x1hi; Xlo = d_x1lo; KT = KT1P; }
    else if (cell == 1) { Whi = d_W2hi; Wlo = d_W2lo; Xhi = d_x2hi; Xlo = d_x2lo; KT = KT23P; }
    else { Whi = d_W3hi; Wlo = d_W3lo; Xhi = d_x3hi; Xlo = d_x3lo; KT = KT23P; }

    int khalf = blockIdx.y;
    int khlen = KT >> 1;
    int ksteps = khlen >> 4;
    int k0 = khalf * khlen;

    int wid = threadIdx.x >> 5, lane = threadIdx.x & 31;
    int g = lane >> 2, t4 = lane & 3;
    int row0 = (blockIdx.x * 4 + wid) * 16;

    const __nv_bfloat16* wh0 = Whi + (size_t)(row0 + g) * KT + k0 + t4 * 2;
    const __nv_bfloat16* wh8 = wh0 + (size_t)8 * KT;
    const __nv_bfloat16* wl0 = Wlo + (size_t)(row0 + g) * KT + k0 + t4 * 2;
    const __nv_bfloat16* wl8 = wl0 + (size_t)8 * KT;

    float acc[4][4];
#pragma unroll
    for (int nt = 0; nt < 4; nt++)
#pragma unroll
        for (int q = 0; q < 4; q++) acc[nt][q] = 0.f;

    for (int ks = 0; ks < ksteps; ks++) {
        int kk = ks * 16;
        uint32_t ah[4], al[4];
        ah[0] = ldu32(wh0 + kk);     ah[1] = ldu32(wh8 + kk);
        ah[2] = ldu32(wh0 + kk + 8); ah[3] = ldu32(wh8 + kk + 8);
        al[0] = ldu32(wl0 + kk);     al[1] = ldu32(wl8 + kk);
        al[2] = ldu32(wl0 + kk + 8); al[3] = ldu32(wl8 + kk + 8);
#pragma unroll
        for (int nt = 0; nt < 4; nt++) {
            const __nv_bfloat16* xh = Xhi + (size_t)(nt * 8 + g) * KT + k0 + kk + t4 * 2;
            const __nv_bfloat16* xl = Xlo + (size_t)(nt * 8 + g) * KT + k0 + kk + t4 * 2;
            uint32_t bh[2], bl[2];
            bh[0] = ldu32(xh); bh[1] = ldu32(xh + 8);
            bl[0] = ldu32(xl); bl[1] = ldu32(xl + 8);
            mma16816(acc[nt], ah, bh);
            mma16816(acc[nt], ah, bl);
            mma16816(acc[nt], al, bh);
        }
    }

    float* gp = d_gp[khalf];
#pragma unroll
    for (int nt = 0; nt < 4; nt++) {
        int r = row0 + g;
        int bcol = nt * 8 + t4 * 2;
        *(float2*)(gp + (size_t)r * BB + bcol) = make_float2(acc[nt][0], acc[nt][1]);
        *(float2*)(gp + (size_t)(r + 8) * BB + bcol) = make_float2(acc[nt][2], acc[nt][3]);
    }
}

/* ---------------- epilogue: partial sum + gates + h/c update ------------- */
__global__ __launch_bounds__(256) void epi_kernel(int cell) {
    const float* cb = cell == 0 ? d_cbias1 : cell == 1 ? d_cbias2 : d_cbias3;
    float* cst = cell == 0 ? d_c1 : cell == 1 ? d_c2 : d_c3;
    float* hst = cell == 0 ? d_h1 : cell == 1 ? d_h2 : d_h3;
    int idx = blockIdx.x * 256 + threadIdx.x;
    int j = idx >> 5, b = idx & 31;
    float g[4];
#pragma unroll
    for (int gt = 0; gt < 4; gt++) {
        size_t o = (size_t)(gt * HH + j) * BB + b;
        g[gt] = d_gp[0][o] + d_gp[1][o] + cb[gt * HH + j];
    }
    float c = sigf(g[1]) * cst[b * HH + j] + sigf(g[0]) * tanhf(g[2]);
    float h = sigf(g[3]) * tanhf(c);
    cst[b * HH + j] = c;
    hst[b * HH + j] = h;
    __nv_bfloat16 hi, lo;
    split_bf16(h, hi, lo);
    if (cell == 0) {
        d_x2hi[b * KT23P + 32 + j] = hi;  d_x2lo[b * KT23P + 32 + j] = lo;
        d_x1hi[b * KT1P + 96 + j] = hi;   d_x1lo[b * KT1P + 96 + j] = lo;
    } else if (cell == 1) {
        d_x3hi[b * KT23P + 32 + j] = hi;  d_x3lo[b * KT23P + 32 + j] = lo;
        d_x2hi[b * KT23P + 1056 + j] = hi; d_x2lo[b * KT23P + 1056 + j] = lo;
    } else {
        d_x3hi[b * KT23P + 1056 + j] = hi; d_x3lo[b * KT23P + 1056 + j] = lo;
    }
}

/* --------------------------- final y (step 59) --------------------------- */
__global__ void ylast_kernel(const float* __restrict__ bout, float* __restrict__ out) {
    __shared__ float red[256];
    int b = blockIdx.x, tid = threadIdx.x;
    int d = tid & 63, seg = tid >> 6;
    const float* hb = d_h3 + b * HH;
    float part = 0.f;
    for (int hh = seg * 256; hh < seg * 256 + 256; hh++)
        part += hb[hh] * d_woutT[hh * DOUT + d];
    red[tid] = part;
    __syncthreads();
    if (tid < 64) {
        float y = bout[tid];
#pragma unroll
        for (int q = 0; q < 4; q++) y += red[q * 64 + tid];
        out[((size_t)b * NSTEPS + (NSTEPS - 1)) * DOUT + tid] = y;
    }
}

/* ------------------------------ launcher --------------------------------- */
extern "C" void kernel_launch(void* const* d_in, const int* in_sizes, int n_in,
                              void* d_out, int out_size) {
    (void)in_sizes; (void)n_in; (void)out_size;
    const float* x    = (const float*)d_in[0];
    const float* w_c1 = (const float*)d_in[1];
    const float* b_c1 = (const float*)d_in[2];
    const float* w_c2 = (const float*)d_in[3];
    const float* b_c2 = (const float*)d_in[4];
    const float* w_c3 = (const float*)d_in[5];
    const float* b_c3 = (const float*)d_in[6];
    const float* w_a1 = (const float*)d_in[7];
    const float* w_a2 = (const float*)d_in[9];
    const float* w_a3 = (const float*)d_in[11];
    const float* wih1 = (const float*)d_in[13];
    const float* whh1 = (const float*)d_in[14];
    const float* bih1 = (const float*)d_in[15];
    const float* bhh1 = (const float*)d_in[16];
    const float* wih2 = (const float*)d_in[17];
    const float* whh2 = (const float*)d_in[18];
    const float* bih2 = (const float*)d_in[19];
    const float* bhh2 = (const float*)d_in[20];
    const float* wih3 = (const float*)d_in[21];
    const float* whh3 = (const float*)d_in[22];
    const float* bih3 = (const float*)d_in[23];
    const float* bhh3 = (const float*)d_in[24];
    const float* wout = (const float*)d_in[25];
    const float* bout = (const float*)d_in[26];
    float* out = (float*)d_out;

    setup_kernel<<<2048, 256>>>(x, wih1, whh1, wih2, whh2, wih3, whh3,
                                bih1, bhh1, bih2, bhh2, bih3, bhh3, wout);
    conv1_kernel<<<dim3(8, C1, BB), 256>>>(x, w_c1, b_c1);
    conv2_kernel<<<dim3(8, C2, BB), 256>>>(w_c2, b_c2);
    conv3_kernel<<<dim3(253, BB), 256>>>(w_c3, b_c3);

    for (int s = 0; s < NSTEPS; s++) {
        pre_kernel<<<128, 256>>>(w_a1, w_a2, w_a3, bout, s, out);
        mm_hmma<<<dim3(64, 2), 128>>>(0);
        epi_kernel<<<128, 256>>>(0);
        mm_hmma<<<dim3(64, 2), 128>>>(1);
        epi_kernel<<<128, 256>>>(1);
        mm_hmma<<<dim3(64, 2), 128>>>(2);
        epi_kernel<<<128, 256>>>(2);
    }
    ylast_kernel<<<32, 256>>>(bout, out);
}